// round 8
// baseline (speedup 1.0000x reference)
#include <cuda_runtime.h>
#include <cstdint>
#include <cstring>

// Problem constants
#define BB     4096
#define D_IN   128
#define HID    200
#define DIMV   256
#define MM     32

// Scratch (device globals — no allocation allowed)
__device__ float g_H1[BB * HID];
__device__ float g_H2[BB * HID];
__device__ float g_Y [BB * DIMV];
__device__ float g_Q [MM * DIMV];

// ---------------------------------------------------------------------------
// Packed f32x2 helpers
// ---------------------------------------------------------------------------
static __device__ __forceinline__ float2 f2fma(float2 a, float2 b, float2 c) {
    unsigned long long ua, ub, uc, ud;
    memcpy(&ua, &a, 8); memcpy(&ub, &b, 8); memcpy(&uc, &c, 8);
    asm("fma.rn.f32x2 %0, %1, %2, %3;" : "=l"(ud) : "l"(ua), "l"(ub), "l"(uc));
    float2 r; memcpy(&r, &ud, 8); return r;
}
static __device__ __forceinline__ float2 f2mul(float2 a, float2 b) {
    unsigned long long ua, ub, ud;
    memcpy(&ua, &a, 8); memcpy(&ub, &b, 8);
    asm("mul.rn.f32x2 %0, %1, %2;" : "=l"(ud) : "l"(ua), "l"(ub));
    float2 r; memcpy(&r, &ud, 8); return r;
}

// ---------------------------------------------------------------------------
// Setup: G = A A^T + 1e-6 I (32x32), Gauss-Jordan inverse, Q = G^{-1} A
// ---------------------------------------------------------------------------
__global__ void setup_kernel(const float* __restrict__ A)
{
    __shared__ float G[32][65];
    __shared__ float fcol[32];
    const int t = threadIdx.x;
    const int i = t >> 5;
    const int j = t & 31;

    float s = 0.f;
    for (int k = 0; k < DIMV; k++)
        s += A[i * DIMV + k] * A[j * DIMV + k];
    G[i][j]      = s + (i == j ? 1e-6f : 0.f);
    G[i][j + 32] = (i == j) ? 1.f : 0.f;
    __syncthreads();

    for (int k = 0; k < 32; k++) {
        if (j == 0) fcol[i] = G[i][k];
        __syncthreads();
        if (i == k) {
            float inv = 1.f / fcol[k];
            G[k][j]      *= inv;
            G[k][j + 32] *= inv;
        }
        __syncthreads();
        if (i != k) {
            float f = fcol[i];
            G[i][j]      -= f * G[k][j];
            G[i][j + 32] -= f * G[k][j + 32];
        }
        __syncthreads();
    }

    for (int r = 0; r < 8; r++) {
        int idx = t + r * 1024;
        int m = idx >> 8;
        int d = idx & 255;
        float acc = 0.f;
        for (int k = 0; k < 32; k++)
            acc += G[m][32 + k] * A[k * DIMV + d];
        g_Q[m * DIMV + d] = acc;
    }
}

// ---------------------------------------------------------------------------
// Tiled GEMM: Y[M,N] = act(X[M,K] @ W[K,N] + bias)
// BM=32, BN=64, BK=32, 128 threads, 4x4 micro-tile.
// Double-buffered smem + register-pipelined inner loop (LDS for kk+1 issued
// before kk's FMAs -> LDS latency hidden). One __syncthreads per k-tile.
// Grid = (N/64, M/32) = 512 CTAs. K and N must be multiples of 4 (true here).
// ---------------------------------------------------------------------------
template<bool RELU>
__global__ __launch_bounds__(128)
void gemm_bias_kernel(const float* __restrict__ X, const float* __restrict__ W,
                      const float* __restrict__ bias, float* __restrict__ Y,
                      int N, int K)
{
    __shared__ float Xs[2][32][36];   // [buf][kk][row]
    __shared__ float Ws[2][32][68];   // [buf][kk][col]
    const int t  = threadIdx.x;
    const int tx = t & 15, ty = t >> 4;        // micro-tile coords
    const int row0 = blockIdx.y * 32;
    const int col0 = blockIdx.x * 64;

    // loader coords
    const int xrow = t >> 3;          // 0..15? no: i>>3 below
    const int nk = (K + 31) / 32;

    // ---- load tile 0 directly into buf 0 ----
    {
#pragma unroll
        for (int l = 0; l < 2; l++) {
            int i = t + l * 128;              // 0..255
            int row = i >> 3;                 // 0..31
            int kq  = i & 7;                  // 0..7 (float4 within BK)
            float4 v = make_float4(0.f, 0.f, 0.f, 0.f);
            if (kq * 4 + 4 <= K)
                v = *(const float4*)&X[(size_t)(row0 + row) * K + kq * 4];
            Xs[0][kq * 4 + 0][row] = v.x;
            Xs[0][kq * 4 + 1][row] = v.y;
            Xs[0][kq * 4 + 2][row] = v.z;
            Xs[0][kq * 4 + 3][row] = v.w;
        }
#pragma unroll
        for (int l = 0; l < 4; l++) {
            int i = t + l * 128;              // 0..511
            int kk = i >> 4;                  // 0..31
            int cq = i & 15;                  // 0..15
            float4 v = make_float4(0.f, 0.f, 0.f, 0.f);
            if (kk < K && col0 + cq * 4 + 4 <= N)
                v = *(const float4*)&W[(size_t)kk * N + col0 + cq * 4];
            *(float4*)&Ws[0][kk][cq * 4] = v;
        }
    }
    __syncthreads();

    float acc[4][4];
#pragma unroll
    for (int i = 0; i < 4; i++)
#pragma unroll
        for (int j = 0; j < 4; j++) acc[i][j] = 0.f;

    for (int kt = 0; kt < nk; kt++) {
        const int buf = kt & 1;
        const int k0n = (kt + 1) * 32;
        const bool more = (kt + 1 < nk);

        // ---- prefetch next tile into registers ----
        float4 px[2], pw[4];
        if (more) {
#pragma unroll
            for (int l = 0; l < 2; l++) {
                int i = t + l * 128;
                int row = i >> 3;
                int kq  = i & 7;
                px[l] = make_float4(0.f, 0.f, 0.f, 0.f);
                if (k0n + kq * 4 + 4 <= K)
                    px[l] = *(const float4*)&X[(size_t)(row0 + row) * K + k0n + kq * 4];
            }
#pragma unroll
            for (int l = 0; l < 4; l++) {
                int i = t + l * 128;
                int kk = i >> 4;
                int cq = i & 15;
                pw[l] = make_float4(0.f, 0.f, 0.f, 0.f);
                if (k0n + kk < K && col0 + cq * 4 + 4 <= N)
                    pw[l] = *(const float4*)&W[(size_t)(k0n + kk) * N + col0 + cq * 4];
            }
        }

        // ---- compute on current buffer, register-pipelined ----
        {
            float4 a_cur = *(const float4*)&Xs[buf][0][ty * 4];
            float4 b_cur = *(const float4*)&Ws[buf][0][tx * 4];
#pragma unroll
            for (int kk = 0; kk < 32; kk++) {
                float4 a_nxt = a_cur, b_nxt = b_cur;
                if (kk < 31) {
                    a_nxt = *(const float4*)&Xs[buf][kk + 1][ty * 4];
                    b_nxt = *(const float4*)&Ws[buf][kk + 1][tx * 4];
                }
                float a4[4] = {a_cur.x, a_cur.y, a_cur.z, a_cur.w};
                float b4[4] = {b_cur.x, b_cur.y, b_cur.z, b_cur.w};
#pragma unroll
                for (int i = 0; i < 4; i++)
#pragma unroll
                    for (int j = 0; j < 4; j++)
                        acc[i][j] += a4[i] * b4[j];
                a_cur = a_nxt; b_cur = b_nxt;
            }
        }

        // ---- stage prefetched tile into the other buffer ----
        if (more) {
            const int nb = buf ^ 1;
#pragma unroll
            for (int l = 0; l < 2; l++) {
                int i = t + l * 128;
                int row = i >> 3;
                int kq  = i & 7;
                Xs[nb][kq * 4 + 0][row] = px[l].x;
                Xs[nb][kq * 4 + 1][row] = px[l].y;
                Xs[nb][kq * 4 + 2][row] = px[l].z;
                Xs[nb][kq * 4 + 3][row] = px[l].w;
            }
#pragma unroll
            for (int l = 0; l < 4; l++) {
                int i = t + l * 128;
                int kk = i >> 4;
                int cq = i & 15;
                *(float4*)&Ws[nb][kk][cq * 4] = pw[l];
            }
        }
        __syncthreads();
    }

#pragma unroll
    for (int i = 0; i < 4; i++) {
        int rr = row0 + ty * 4 + i;
#pragma unroll
        for (int j = 0; j < 4; j++) {
            int cc = col0 + tx * 4 + j;
            if (cc < N) {
                float v = acc[i][j] + bias[cc];
                if (RELU) v = fmaxf(v, 0.f);
                Y[(size_t)rr * N + cc] = v;
            }
        }
    }
}

// ---------------------------------------------------------------------------
// Iteration kernel: warp-per-4-rows, z in registers, f32x2 math,
// warp-autonomous early exit on max|v - u| < TOL.
// Calibration: rel_err ~ 1.5e-6 floor for TOL in [1e-6, 1e-3]
// (residual collapses super-geometrically once active set stabilizes).
// ---------------------------------------------------------------------------
#define DR_TOL 5e-3f

__global__ __launch_bounds__(128, 2)
void iter_kernel(const float* __restrict__ bmat,
                 const float* __restrict__ A,
                 const int*   __restrict__ n_iter_ptr,
                 float* __restrict__ out)
{
    extern __shared__ float smem[];
    float* As = smem;          // 32*256
    float* Qs = smem + 8192;   // 32*256
    const int t = threadIdx.x;
    for (int i = t; i < 8192; i += 128) {
        As[i] = A[i];
        Qs[i] = g_Q[i];
    }
    __syncthreads();

    const int lane = t & 31;
    const int w    = t >> 5;
    const int rowbase = blockIdx.x * 16 + w * 4;

    const float4* As4 = (const float4*)As;
    const float4* Qs4 = (const float4*)Qs;

    float2 z[4][4];
#pragma unroll
    for (int r = 0; r < 4; r++) {
        const float4* y = (const float4*)(g_Y + (size_t)(rowbase + r) * DIMV);
        float4 lo = y[2 * lane];
        float4 hi = y[2 * lane + 1];
        z[r][0] = make_float2(lo.x, lo.y); z[r][1] = make_float2(lo.z, lo.w);
        z[r][2] = make_float2(hi.x, hi.y); z[r][3] = make_float2(hi.z, hi.w);
    }

    float2 nc[4][4];
#pragma unroll
    for (int r = 0; r < 4; r++)
#pragma unroll
        for (int k = 0; k < 4; k++) nc[r][k] = make_float2(0.f, 0.f);
    for (int m = 0; m < MM; m++) {
        float4 qlo = Qs4[m * 64 + 2 * lane];
        float4 qhi = Qs4[m * 64 + 2 * lane + 1];
        float2 q0 = make_float2(qlo.x, qlo.y), q1 = make_float2(qlo.z, qlo.w);
        float2 q2 = make_float2(qhi.x, qhi.y), q3 = make_float2(qhi.z, qhi.w);
#pragma unroll
        for (int r = 0; r < 4; r++) {
            float bv = -bmat[(size_t)(rowbase + r) * MM + m];
            float2 b2 = make_float2(bv, bv);
            nc[r][0] = f2fma(b2, q0, nc[r][0]);
            nc[r][1] = f2fma(b2, q1, nc[r][1]);
            nc[r][2] = f2fma(b2, q2, nc[r][2]);
            nc[r][3] = f2fma(b2, q3, nc[r][3]);
        }
    }

    const int niter = *n_iter_ptr;
    const unsigned FULL = 0xffffffffu;
    float2 u[4][4];

    for (int it = 0; ; ++it) {
        // ---- compute u = p_aff(z) ----
        {
            float p0[32], p1[32], p2[32], p3[32];
#pragma unroll
            for (int m = 0; m < 32; m++) {
                float4 alo = As4[m * 64 + 2 * lane];
                float4 ahi = As4[m * 64 + 2 * lane + 1];
                float2 a0 = make_float2(alo.x, alo.y), a1 = make_float2(alo.z, alo.w);
                float2 a2 = make_float2(ahi.x, ahi.y), a3 = make_float2(ahi.z, ahi.w);
                float2 pp;
                pp = f2mul(z[0][0], a0); pp = f2fma(z[0][1], a1, pp);
                pp = f2fma(z[0][2], a2, pp); pp = f2fma(z[0][3], a3, pp);
                p0[m] = pp.x + pp.y;
                pp = f2mul(z[1][0], a0); pp = f2fma(z[1][1], a1, pp);
                pp = f2fma(z[1][2], a2, pp); pp = f2fma(z[1][3], a3, pp);
                p1[m] = pp.x + pp.y;
                pp = f2mul(z[2][0], a0); pp = f2fma(z[2][1], a1, pp);
                pp = f2fma(z[2][2], a2, pp); pp = f2fma(z[2][3], a3, pp);
                p2[m] = pp.x + pp.y;
                pp = f2mul(z[3][0], a0); pp = f2fma(z[3][1], a1, pp);
                pp = f2fma(z[3][2], a2, pp); pp = f2fma(z[3][3], a3, pp);
                p3[m] = pp.x + pp.y;
            }
#pragma unroll
            for (int s = 16; s >= 1; s >>= 1) {
#pragma unroll
                for (int i = 0; i < s; i++) {
                    float aa, bb, send, recv;
                    aa = p0[i]; bb = p0[i + s];
                    send = (lane & s) ? aa : bb; recv = __shfl_xor_sync(FULL, send, s);
                    p0[i] = ((lane & s) ? bb : aa) + recv;
                    aa = p1[i]; bb = p1[i + s];
                    send = (lane & s) ? aa : bb; recv = __shfl_xor_sync(FULL, send, s);
                    p1[i] = ((lane & s) ? bb : aa) + recv;
                    aa = p2[i]; bb = p2[i + s];
                    send = (lane & s) ? aa : bb; recv = __shfl_xor_sync(FULL, send, s);
                    p2[i] = ((lane & s) ? bb : aa) + recv;
                    aa = p3[i]; bb = p3[i + s];
                    send = (lane & s) ? aa : bb; recv = __shfl_xor_sync(FULL, send, s);
                    p3[i] = ((lane & s) ? bb : aa) + recv;
                }
            }
            const float r0 = p0[0], r1 = p1[0], r2 = p2[0], r3 = p3[0];

            float2 acc[4][4];
#pragma unroll
            for (int r = 0; r < 4; r++)
#pragma unroll
                for (int k = 0; k < 4; k++) acc[r][k] = nc[r][k];
#pragma unroll
            for (int m = 0; m < 32; m++) {
                float rm0 = __shfl_sync(FULL, r0, m);
                float rm1 = __shfl_sync(FULL, r1, m);
                float rm2 = __shfl_sync(FULL, r2, m);
                float rm3 = __shfl_sync(FULL, r3, m);
                float4 qlo = Qs4[m * 64 + 2 * lane];
                float4 qhi = Qs4[m * 64 + 2 * lane + 1];
                float2 q0 = make_float2(qlo.x, qlo.y), q1 = make_float2(qlo.z, qlo.w);
                float2 q2 = make_float2(qhi.x, qhi.y), q3 = make_float2(qhi.z, qhi.w);
                float2 v;
                v = make_float2(rm0, rm0);
                acc[0][0] = f2fma(v, q0, acc[0][0]); acc[0][1] = f2fma(v, q1, acc[0][1]);
                acc[0][2] = f2fma(v, q2, acc[0][2]); acc[0][3] = f2fma(v, q3, acc[0][3]);
                v = make_float2(rm1, rm1);
                acc[1][0] = f2fma(v, q0, acc[1][0]); acc[1][1] = f2fma(v, q1, acc[1][1]);
                acc[1][2] = f2fma(v, q2, acc[1][2]); acc[1][3] = f2fma(v, q3, acc[1][3]);
                v = make_float2(rm2, rm2);
                acc[2][0] = f2fma(v, q0, acc[2][0]); acc[2][1] = f2fma(v, q1, acc[2][1]);
                acc[2][2] = f2fma(v, q2, acc[2][2]); acc[2][3] = f2fma(v, q3, acc[2][3]);
                v = make_float2(rm3, rm3);
                acc[3][0] = f2fma(v, q0, acc[3][0]); acc[3][1] = f2fma(v, q1, acc[3][1]);
                acc[3][2] = f2fma(v, q2, acc[3][2]); acc[3][3] = f2fma(v, q3, acc[3][3]);
            }
            const float2 NEG1 = make_float2(-1.f, -1.f);
#pragma unroll
            for (int r = 0; r < 4; r++)
#pragma unroll
                for (int k = 0; k < 4; k++)
                    u[r][k] = f2fma(acc[r][k], NEG1, z[r][k]);
        }

        if (it >= niter) break;

        // ---- z update + residual tracking ----
        float dmax = 0.f;
#pragma unroll
        for (int r = 0; r < 4; r++) {
#pragma unroll
            for (int k = 0; k < 4; k++) {
                float vx = fminf(fmaxf(2.f * u[r][k].x - z[r][k].x, 0.f), 1.f);
                float vy = fminf(fmaxf(2.f * u[r][k].y - z[r][k].y, 0.f), 1.f);
                float dx = vx - u[r][k].x;
                float dy = vy - u[r][k].y;
                z[r][k].x = fmaf(1.7f, dx, z[r][k].x);
                z[r][k].y = fmaf(1.7f, dy, z[r][k].y);
                dmax = fmaxf(dmax, fabsf(dx));
                dmax = fmaxf(dmax, fabsf(dy));
            }
        }
        if (__all_sync(FULL, dmax < DR_TOL)) it = niter - 1;
    }

    // store out = p_aff(z_final) = u
#pragma unroll
    for (int r = 0; r < 4; r++) {
        float4* o = (float4*)(out + (size_t)(rowbase + r) * DIMV);
        float4 lo, hi;
        lo.x = u[r][0].x; lo.y = u[r][0].y; lo.z = u[r][1].x; lo.w = u[r][1].y;
        hi.x = u[r][2].x; hi.y = u[r][2].y; hi.z = u[r][3].x; hi.w = u[r][3].y;
        o[2 * lane]     = lo;
        o[2 * lane + 1] = hi;
    }
}

// ---------------------------------------------------------------------------
// Launch
// ---------------------------------------------------------------------------
extern "C" void kernel_launch(void* const* d_in, const int* in_sizes, int n_in,
                              void* d_out, int out_size)
{
    const float* x   = (const float*)d_in[0];
    const float* b   = (const float*)d_in[1];
    const float* W1  = (const float*)d_in[2];
    const float* b1  = (const float*)d_in[3];
    const float* W2  = (const float*)d_in[4];
    const float* b2  = (const float*)d_in[5];
    const float* W3  = (const float*)d_in[6];
    const float* b3  = (const float*)d_in[7];
    const float* A   = (const float*)d_in[8];
    const int* n_it  = (const int*)d_in[10];
    float* out = (float*)d_out;

    setup_kernel<<<1, 1024>>>(A);

    float* h1; cudaGetSymbolAddress((void**)&h1, g_H1);
    float* h2; cudaGetSymbolAddress((void**)&h2, g_H2);
    float* y;  cudaGetSymbolAddress((void**)&y,  g_Y);

    gemm_bias_kernel<true ><<<dim3((HID  + 63) / 64, BB / 32), 128>>>(x,  W1, b1, h1, HID,  D_IN);
    gemm_bias_kernel<true ><<<dim3((HID  + 63) / 64, BB / 32), 128>>>(h1, W2, b2, h2, HID,  HID);
    gemm_bias_kernel<false><<<dim3((DIMV + 63) / 64, BB / 32), 128>>>(h2, W3, b3, y,  DIMV, HID);

    cudaFuncSetAttribute(iter_kernel, cudaFuncAttributeMaxDynamicSharedMemorySize, 65536);
    iter_kernel<<<BB / 16, 128, 65536>>>(b, A, n_it, out);
}

// round 9
// speedup vs baseline: 1.4213x; 1.4213x over previous
#include <cuda_runtime.h>
#include <cstdint>
#include <cstring>

// Problem constants
#define BB     4096
#define D_IN   128
#define HID    200
#define DIMV   256
#define MM     32

// Scratch (device globals — no allocation allowed)
__device__ float g_H1[BB * HID];
__device__ float g_H2[BB * HID];
__device__ float g_Y [BB * DIMV];
__device__ float g_Q [MM * DIMV];

// ---------------------------------------------------------------------------
// Packed f32x2 helpers
// ---------------------------------------------------------------------------
static __device__ __forceinline__ float2 f2fma(float2 a, float2 b, float2 c) {
    unsigned long long ua, ub, uc, ud;
    memcpy(&ua, &a, 8); memcpy(&ub, &b, 8); memcpy(&uc, &c, 8);
    asm("fma.rn.f32x2 %0, %1, %2, %3;" : "=l"(ud) : "l"(ua), "l"(ub), "l"(uc));
    float2 r; memcpy(&r, &ud, 8); return r;
}
static __device__ __forceinline__ float2 f2mul(float2 a, float2 b) {
    unsigned long long ua, ub, ud;
    memcpy(&ua, &a, 8); memcpy(&ub, &b, 8);
    asm("mul.rn.f32x2 %0, %1, %2;" : "=l"(ud) : "l"(ua), "l"(ub));
    float2 r; memcpy(&r, &ud, 8); return r;
}

// ---------------------------------------------------------------------------
// Setup: G = A A^T + 1e-6 I (32x32), Gauss-Jordan inverse, Q = G^{-1} A
// ---------------------------------------------------------------------------
__global__ void setup_kernel(const float* __restrict__ A)
{
    __shared__ float G[32][65];
    __shared__ float fcol[32];
    const int t = threadIdx.x;
    const int i = t >> 5;
    const int j = t & 31;

    float s = 0.f;
    for (int k = 0; k < DIMV; k++)
        s += A[i * DIMV + k] * A[j * DIMV + k];
    G[i][j]      = s + (i == j ? 1e-6f : 0.f);
    G[i][j + 32] = (i == j) ? 1.f : 0.f;
    __syncthreads();

    for (int k = 0; k < 32; k++) {
        if (j == 0) fcol[i] = G[i][k];
        __syncthreads();
        if (i == k) {
            float inv = 1.f / fcol[k];
            G[k][j]      *= inv;
            G[k][j + 32] *= inv;
        }
        __syncthreads();
        if (i != k) {
            float f = fcol[i];
            G[i][j]      -= f * G[k][j];
            G[i][j + 32] -= f * G[k][j + 32];
        }
        __syncthreads();
    }

    for (int r = 0; r < 8; r++) {
        int idx = t + r * 1024;
        int m = idx >> 8;
        int d = idx & 255;
        float acc = 0.f;
        for (int k = 0; k < 32; k++)
            acc += G[m][32 + k] * A[k * DIMV + d];
        g_Q[m * DIMV + d] = acc;
    }
}

// ---------------------------------------------------------------------------
// Tiled GEMM: Y[M,N] = act(X[M,K] @ W[K,N] + bias)
// BM=32, BN=64, BK=16, 256 threads, 2x4 micro-tile, double-buffered smem
// (one __syncthreads per k-tile). Grid = (N/64, M/32) = 512 CTAs.
// [R7-proven: 29.2us/layer. R8's 128-thread BK=32 variant regressed.]
// ---------------------------------------------------------------------------
template<bool RELU>
__global__ __launch_bounds__(256)
void gemm_bias_kernel(const float* __restrict__ X, const float* __restrict__ W,
                      const float* __restrict__ bias, float* __restrict__ Y,
                      int N, int K)
{
    __shared__ float Xs[2][16][36];   // [buf][kk][row], padded
    __shared__ float Ws[2][16][68];   // [buf][kk][col], padded
    const int t  = threadIdx.x;
    const int tx = t & 15, ty = t >> 4;
    const int row0 = blockIdx.y * 32;
    const int col0 = blockIdx.x * 64;

    // loader coords
    const int xr = t >> 3;          // 0..31 (row)
    const int xq = (t & 7) * 2;     // k pair
    const int wk = t >> 4;          // 0..15 (k)
    const int wc = (t & 15) * 4;    // col quad

    const int nk = (K + 15) / 16;

    // preload tile 0 into buf 0
    {
#pragma unroll
        for (int i = 0; i < 2; i++) {
            int kk = xq + i;
            float v = (kk < K) ? X[(size_t)(row0 + xr) * K + kk] : 0.f;
            Xs[0][xq + i][xr] = v;
        }
#pragma unroll
        for (int j = 0; j < 4; j++) {
            float v = 0.f;
            if (wk < K && col0 + wc + j < N) v = W[(size_t)wk * N + col0 + wc + j];
            Ws[0][wk][wc + j] = v;
        }
    }
    __syncthreads();

    float acc[2][4];
#pragma unroll
    for (int i = 0; i < 2; i++)
#pragma unroll
        for (int j = 0; j < 4; j++) acc[i][j] = 0.f;

    for (int kt = 0; kt < nk; kt++) {
        const int buf = kt & 1;
        const int k0n = (kt + 1) * 16;

        // prefetch next tile into registers
        float px[2], pw[4];
        if (kt + 1 < nk) {
#pragma unroll
            for (int i = 0; i < 2; i++) {
                int kk = k0n + xq + i;
                px[i] = (kk < K) ? X[(size_t)(row0 + xr) * K + kk] : 0.f;
            }
#pragma unroll
            for (int j = 0; j < 4; j++) {
                int kk = k0n + wk;
                pw[j] = 0.f;
                if (kk < K && col0 + wc + j < N) pw[j] = W[(size_t)kk * N + col0 + wc + j];
            }
        }

        // compute on current buffer
#pragma unroll
        for (int kk = 0; kk < 16; kk++) {
            float a0 = Xs[buf][kk][ty * 2];
            float a1 = Xs[buf][kk][ty * 2 + 1];
            float4 bv = *(const float4*)&Ws[buf][kk][tx * 4];
            float b4[4] = {bv.x, bv.y, bv.z, bv.w};
#pragma unroll
            for (int j = 0; j < 4; j++) {
                acc[0][j] += a0 * b4[j];
                acc[1][j] += a1 * b4[j];
            }
        }

        // stage prefetched tile into the other buffer
        if (kt + 1 < nk) {
            const int nb = buf ^ 1;
#pragma unroll
            for (int i = 0; i < 2; i++) Xs[nb][xq + i][xr] = px[i];
#pragma unroll
            for (int j = 0; j < 4; j++) Ws[nb][wk][wc + j] = pw[j];
        }
        __syncthreads();
    }

#pragma unroll
    for (int i = 0; i < 2; i++) {
        int rr = row0 + ty * 2 + i;
#pragma unroll
        for (int j = 0; j < 4; j++) {
            int cc = col0 + tx * 4 + j;
            if (cc < N) {
                float v = acc[i][j] + bias[cc];
                if (RELU) v = fmaxf(v, 0.f);
                Y[(size_t)rr * N + cc] = v;
            }
        }
    }
}

// ---------------------------------------------------------------------------
// Iteration kernel: warp-per-4-rows, z in registers, f32x2 math,
// warp-autonomous early exit on max|v - u| < TOL.
// Calibration: rel_err ~1.5e-6 floor for TOL in [1e-6, 1e-3]; TOL=1e-3 proven
// at 334.3us total. [R8's TOL=5e-3 run regressed unexplainedly; reverted.]
// ---------------------------------------------------------------------------
#define DR_TOL 1e-3f

__global__ __launch_bounds__(128, 2)
void iter_kernel(const float* __restrict__ bmat,
                 const float* __restrict__ A,
                 const int*   __restrict__ n_iter_ptr,
                 float* __restrict__ out)
{
    extern __shared__ float smem[];
    float* As = smem;          // 32*256
    float* Qs = smem + 8192;   // 32*256
    const int t = threadIdx.x;
    for (int i = t; i < 8192; i += 128) {
        As[i] = A[i];
        Qs[i] = g_Q[i];
    }
    __syncthreads();

    const int lane = t & 31;
    const int w    = t >> 5;
    const int rowbase = blockIdx.x * 16 + w * 4;

    const float4* As4 = (const float4*)As;
    const float4* Qs4 = (const float4*)Qs;

    float2 z[4][4];
#pragma unroll
    for (int r = 0; r < 4; r++) {
        const float4* y = (const float4*)(g_Y + (size_t)(rowbase + r) * DIMV);
        float4 lo = y[2 * lane];
        float4 hi = y[2 * lane + 1];
        z[r][0] = make_float2(lo.x, lo.y); z[r][1] = make_float2(lo.z, lo.w);
        z[r][2] = make_float2(hi.x, hi.y); z[r][3] = make_float2(hi.z, hi.w);
    }

    float2 nc[4][4];
#pragma unroll
    for (int r = 0; r < 4; r++)
#pragma unroll
        for (int k = 0; k < 4; k++) nc[r][k] = make_float2(0.f, 0.f);
    for (int m = 0; m < MM; m++) {
        float4 qlo = Qs4[m * 64 + 2 * lane];
        float4 qhi = Qs4[m * 64 + 2 * lane + 1];
        float2 q0 = make_float2(qlo.x, qlo.y), q1 = make_float2(qlo.z, qlo.w);
        float2 q2 = make_float2(qhi.x, qhi.y), q3 = make_float2(qhi.z, qhi.w);
#pragma unroll
        for (int r = 0; r < 4; r++) {
            float bv = -bmat[(size_t)(rowbase + r) * MM + m];
            float2 b2 = make_float2(bv, bv);
            nc[r][0] = f2fma(b2, q0, nc[r][0]);
            nc[r][1] = f2fma(b2, q1, nc[r][1]);
            nc[r][2] = f2fma(b2, q2, nc[r][2]);
            nc[r][3] = f2fma(b2, q3, nc[r][3]);
        }
    }

    const int niter = *n_iter_ptr;
    const unsigned FULL = 0xffffffffu;
    float2 u[4][4];

    for (int it = 0; ; ++it) {
        // ---- compute u = p_aff(z) ----
        {
            float p0[32], p1[32], p2[32], p3[32];
#pragma unroll
            for (int m = 0; m < 32; m++) {
                float4 alo = As4[m * 64 + 2 * lane];
                float4 ahi = As4[m * 64 + 2 * lane + 1];
                float2 a0 = make_float2(alo.x, alo.y), a1 = make_float2(alo.z, alo.w);
                float2 a2 = make_float2(ahi.x, ahi.y), a3 = make_float2(ahi.z, ahi.w);
                float2 pp;
                pp = f2mul(z[0][0], a0); pp = f2fma(z[0][1], a1, pp);
                pp = f2fma(z[0][2], a2, pp); pp = f2fma(z[0][3], a3, pp);
                p0[m] = pp.x + pp.y;
                pp = f2mul(z[1][0], a0); pp = f2fma(z[1][1], a1, pp);
                pp = f2fma(z[1][2], a2, pp); pp = f2fma(z[1][3], a3, pp);
                p1[m] = pp.x + pp.y;
                pp = f2mul(z[2][0], a0); pp = f2fma(z[2][1], a1, pp);
                pp = f2fma(z[2][2], a2, pp); pp = f2fma(z[2][3], a3, pp);
                p2[m] = pp.x + pp.y;
                pp = f2mul(z[3][0], a0); pp = f2fma(z[3][1], a1, pp);
                pp = f2fma(z[3][2], a2, pp); pp = f2fma(z[3][3], a3, pp);
                p3[m] = pp.x + pp.y;
            }
#pragma unroll
            for (int s = 16; s >= 1; s >>= 1) {
#pragma unroll
                for (int i = 0; i < s; i++) {
                    float aa, bb, send, recv;
                    aa = p0[i]; bb = p0[i + s];
                    send = (lane & s) ? aa : bb; recv = __shfl_xor_sync(FULL, send, s);
                    p0[i] = ((lane & s) ? bb : aa) + recv;
                    aa = p1[i]; bb = p1[i + s];
                    send = (lane & s) ? aa : bb; recv = __shfl_xor_sync(FULL, send, s);
                    p1[i] = ((lane & s) ? bb : aa) + recv;
                    aa = p2[i]; bb = p2[i + s];
                    send = (lane & s) ? aa : bb; recv = __shfl_xor_sync(FULL, send, s);
                    p2[i] = ((lane & s) ? bb : aa) + recv;
                    aa = p3[i]; bb = p3[i + s];
                    send = (lane & s) ? aa : bb; recv = __shfl_xor_sync(FULL, send, s);
                    p3[i] = ((lane & s) ? bb : aa) + recv;
                }
            }
            const float r0 = p0[0], r1 = p1[0], r2 = p2[0], r3 = p3[0];

            float2 acc[4][4];
#pragma unroll
            for (int r = 0; r < 4; r++)
#pragma unroll
                for (int k = 0; k < 4; k++) acc[r][k] = nc[r][k];
#pragma unroll
            for (int m = 0; m < 32; m++) {
                float rm0 = __shfl_sync(FULL, r0, m);
                float rm1 = __shfl_sync(FULL, r1, m);
                float rm2 = __shfl_sync(FULL, r2, m);
                float rm3 = __shfl_sync(FULL, r3, m);
                float4 qlo = Qs4[m * 64 + 2 * lane];
                float4 qhi = Qs4[m * 64 + 2 * lane + 1];
                float2 q0 = make_float2(qlo.x, qlo.y), q1 = make_float2(qlo.z, qlo.w);
                float2 q2 = make_float2(qhi.x, qhi.y), q3 = make_float2(qhi.z, qhi.w);
                float2 v;
                v = make_float2(rm0, rm0);
                acc[0][0] = f2fma(v, q0, acc[0][0]); acc[0][1] = f2fma(v, q1, acc[0][1]);
                acc[0][2] = f2fma(v, q2, acc[0][2]); acc[0][3] = f2fma(v, q3, acc[0][3]);
                v = make_float2(rm1, rm1);
                acc[1][0] = f2fma(v, q0, acc[1][0]); acc[1][1] = f2fma(v, q1, acc[1][1]);
                acc[1][2] = f2fma(v, q2, acc[1][2]); acc[1][3] = f2fma(v, q3, acc[1][3]);
                v = make_float2(rm2, rm2);
                acc[2][0] = f2fma(v, q0, acc[2][0]); acc[2][1] = f2fma(v, q1, acc[2][1]);
                acc[2][2] = f2fma(v, q2, acc[2][2]); acc[2][3] = f2fma(v, q3, acc[2][3]);
                v = make_float2(rm3, rm3);
                acc[3][0] = f2fma(v, q0, acc[3][0]); acc[3][1] = f2fma(v, q1, acc[3][1]);
                acc[3][2] = f2fma(v, q2, acc[3][2]); acc[3][3] = f2fma(v, q3, acc[3][3]);
            }
            const float2 NEG1 = make_float2(-1.f, -1.f);
#pragma unroll
            for (int r = 0; r < 4; r++)
#pragma unroll
                for (int k = 0; k < 4; k++)
                    u[r][k] = f2fma(acc[r][k], NEG1, z[r][k]);
        }

        if (it >= niter) break;

        // ---- z update + residual tracking ----
        float dmax = 0.f;
#pragma unroll
        for (int r = 0; r < 4; r++) {
#pragma unroll
            for (int k = 0; k < 4; k++) {
                float vx = fminf(fmaxf(2.f * u[r][k].x - z[r][k].x, 0.f), 1.f);
                float vy = fminf(fmaxf(2.f * u[r][k].y - z[r][k].y, 0.f), 1.f);
                float dx = vx - u[r][k].x;
                float dy = vy - u[r][k].y;
                z[r][k].x = fmaf(1.7f, dx, z[r][k].x);
                z[r][k].y = fmaf(1.7f, dy, z[r][k].y);
                dmax = fmaxf(dmax, fabsf(dx));
                dmax = fmaxf(dmax, fabsf(dy));
            }
        }
        if (__all_sync(FULL, dmax < DR_TOL)) it = niter - 1;
    }

    // store out = p_aff(z_final) = u
#pragma unroll
    for (int r = 0; r < 4; r++) {
        float4* o = (float4*)(out + (size_t)(rowbase + r) * DIMV);
        float4 lo, hi;
        lo.x = u[r][0].x; lo.y = u[r][0].y; lo.z = u[r][1].x; lo.w = u[r][1].y;
        hi.x = u[r][2].x; hi.y = u[r][2].y; hi.z = u[r][3].x; hi.w = u[r][3].y;
        o[2 * lane]     = lo;
        o[2 * lane + 1] = hi;
    }
}

// ---------------------------------------------------------------------------
// Launch
// ---------------------------------------------------------------------------
extern "C" void kernel_launch(void* const* d_in, const int* in_sizes, int n_in,
                              void* d_out, int out_size)
{
    const float* x   = (const float*)d_in[0];
    const float* b   = (const float*)d_in[1];
    const float* W1  = (const float*)d_in[2];
    const float* b1  = (const float*)d_in[3];
    const float* W2  = (const float*)d_in[4];
    const float* b2  = (const float*)d_in[5];
    const float* W3  = (const float*)d_in[6];
    const float* b3  = (const float*)d_in[7];
    const float* A   = (const float*)d_in[8];
    const int* n_it  = (const int*)d_in[10];
    float* out = (float*)d_out;

    setup_kernel<<<1, 1024>>>(A);

    float* h1; cudaGetSymbolAddress((void**)&h1, g_H1);
    float* h2; cudaGetSymbolAddress((void**)&h2, g_H2);
    float* y;  cudaGetSymbolAddress((void**)&y,  g_Y);

    gemm_bias_kernel<true ><<<dim3((HID  + 63) / 64, BB / 32), 256>>>(x,  W1, b1, h1, HID,  D_IN);
    gemm_bias_kernel<true ><<<dim3((HID  + 63) / 64, BB / 32), 256>>>(h1, W2, b2, h2, HID,  HID);
    gemm_bias_kernel<false><<<dim3((DIMV + 63) / 64, BB / 32), 256>>>(h2, W3, b3, y,  DIMV, HID);

    cudaFuncSetAttribute(iter_kernel, cudaFuncAttributeMaxDynamicSharedMemorySize, 65536);
    iter_kernel<<<BB / 16, 128, 65536>>>(b, A, n_it, out);
}

// round 10
// speedup vs baseline: 1.4331x; 1.0083x over previous
#include <cuda_runtime.h>
#include <cstdint>
#include <cstring>

// Problem constants
#define BB     4096
#define D_IN   128
#define HID    200
#define DIMV   256
#define MM     32
#define NTASKS (BB / 4)   // 4 rows per task

// Scratch (device globals — no allocation allowed)
__device__ float g_H1[BB * HID];
__device__ float g_H2[BB * HID];
__device__ float g_Y [BB * DIMV];
__device__ float g_Q [MM * DIMV];
__device__ int   g_ctr;            // work-queue counter (reset by setup_kernel)

// ---------------------------------------------------------------------------
// Packed f32x2 helpers
// ---------------------------------------------------------------------------
static __device__ __forceinline__ float2 f2fma(float2 a, float2 b, float2 c) {
    unsigned long long ua, ub, uc, ud;
    memcpy(&ua, &a, 8); memcpy(&ub, &b, 8); memcpy(&uc, &c, 8);
    asm("fma.rn.f32x2 %0, %1, %2, %3;" : "=l"(ud) : "l"(ua), "l"(ub), "l"(uc));
    float2 r; memcpy(&r, &ud, 8); return r;
}
static __device__ __forceinline__ float2 f2mul(float2 a, float2 b) {
    unsigned long long ua, ub, ud;
    memcpy(&ua, &a, 8); memcpy(&ub, &b, 8);
    asm("mul.rn.f32x2 %0, %1, %2;" : "=l"(ud) : "l"(ua), "l"(ub));
    float2 r; memcpy(&r, &ud, 8); return r;
}

// ---------------------------------------------------------------------------
// Setup: G = A A^T + 1e-6 I (32x32), Gauss-Jordan inverse, Q = G^{-1} A.
// Also resets the work-queue counter (runs before iter_kernel every launch).
// ---------------------------------------------------------------------------
__global__ void setup_kernel(const float* __restrict__ A)
{
    __shared__ float G[32][65];
    __shared__ float fcol[32];
    const int t = threadIdx.x;
    const int i = t >> 5;
    const int j = t & 31;

    if (t == 0) g_ctr = 0;

    float s = 0.f;
    for (int k = 0; k < DIMV; k++)
        s += A[i * DIMV + k] * A[j * DIMV + k];
    G[i][j]      = s + (i == j ? 1e-6f : 0.f);
    G[i][j + 32] = (i == j) ? 1.f : 0.f;
    __syncthreads();

    for (int k = 0; k < 32; k++) {
        if (j == 0) fcol[i] = G[i][k];
        __syncthreads();
        if (i == k) {
            float inv = 1.f / fcol[k];
            G[k][j]      *= inv;
            G[k][j + 32] *= inv;
        }
        __syncthreads();
        if (i != k) {
            float f = fcol[i];
            G[i][j]      -= f * G[k][j];
            G[i][j + 32] -= f * G[k][j + 32];
        }
        __syncthreads();
    }

    for (int r = 0; r < 8; r++) {
        int idx = t + r * 1024;
        int m = idx >> 8;
        int d = idx & 255;
        float acc = 0.f;
        for (int k = 0; k < 32; k++)
            acc += G[m][32 + k] * A[k * DIMV + d];
        g_Q[m * DIMV + d] = acc;
    }
}

// ---------------------------------------------------------------------------
// Tiled GEMM: Y[M,N] = act(X[M,K] @ W[K,N] + bias)
// BM=32, BN=64, BK=16, 256 threads, 2x4 micro-tile, double-buffered smem.
// [R7/R9-proven: 29.2us/layer]
// ---------------------------------------------------------------------------
template<bool RELU>
__global__ __launch_bounds__(256)
void gemm_bias_kernel(const float* __restrict__ X, const float* __restrict__ W,
                      const float* __restrict__ bias, float* __restrict__ Y,
                      int N, int K)
{
    __shared__ float Xs[2][16][36];
    __shared__ float Ws[2][16][68];
    const int t  = threadIdx.x;
    const int tx = t & 15, ty = t >> 4;
    const int row0 = blockIdx.y * 32;
    const int col0 = blockIdx.x * 64;

    const int xr = t >> 3;
    const int xq = (t & 7) * 2;
    const int wk = t >> 4;
    const int wc = (t & 15) * 4;

    const int nk = (K + 15) / 16;

    {
#pragma unroll
        for (int i = 0; i < 2; i++) {
            int kk = xq + i;
            float v = (kk < K) ? X[(size_t)(row0 + xr) * K + kk] : 0.f;
            Xs[0][xq + i][xr] = v;
        }
#pragma unroll
        for (int j = 0; j < 4; j++) {
            float v = 0.f;
            if (wk < K && col0 + wc + j < N) v = W[(size_t)wk * N + col0 + wc + j];
            Ws[0][wk][wc + j] = v;
        }
    }
    __syncthreads();

    float acc[2][4];
#pragma unroll
    for (int i = 0; i < 2; i++)
#pragma unroll
        for (int j = 0; j < 4; j++) acc[i][j] = 0.f;

    for (int kt = 0; kt < nk; kt++) {
        const int buf = kt & 1;
        const int k0n = (kt + 1) * 16;

        float px[2], pw[4];
        if (kt + 1 < nk) {
#pragma unroll
            for (int i = 0; i < 2; i++) {
                int kk = k0n + xq + i;
                px[i] = (kk < K) ? X[(size_t)(row0 + xr) * K + kk] : 0.f;
            }
#pragma unroll
            for (int j = 0; j < 4; j++) {
                int kk = k0n + wk;
                pw[j] = 0.f;
                if (kk < K && col0 + wc + j < N) pw[j] = W[(size_t)kk * N + col0 + wc + j];
            }
        }

#pragma unroll
        for (int kk = 0; kk < 16; kk++) {
            float a0 = Xs[buf][kk][ty * 2];
            float a1 = Xs[buf][kk][ty * 2 + 1];
            float4 bv = *(const float4*)&Ws[buf][kk][tx * 4];
            float b4[4] = {bv.x, bv.y, bv.z, bv.w};
#pragma unroll
            for (int j = 0; j < 4; j++) {
                acc[0][j] += a0 * b4[j];
                acc[1][j] += a1 * b4[j];
            }
        }

        if (kt + 1 < nk) {
            const int nb = buf ^ 1;
#pragma unroll
            for (int i = 0; i < 2; i++) Xs[nb][xq + i][xr] = px[i];
#pragma unroll
            for (int j = 0; j < 4; j++) Ws[nb][wk][wc + j] = pw[j];
        }
        __syncthreads();
    }

#pragma unroll
    for (int i = 0; i < 2; i++) {
        int rr = row0 + ty * 2 + i;
#pragma unroll
        for (int j = 0; j < 4; j++) {
            int cc = col0 + tx * 4 + j;
            if (cc < N) {
                float v = acc[i][j] + bias[cc];
                if (RELU) v = fmaxf(v, 0.f);
                Y[(size_t)rr * N + cc] = v;
            }
        }
    }
}

// ---------------------------------------------------------------------------
// Persistent iteration kernel: grid = 148 CTAs x 256 thr (8 warps/SM).
// Warps pull 4-row tasks from a global atomic queue until empty -> load is
// balanced at avg-iterations-per-task instead of max-per-SM, and the 256-CTA
// half-wave imbalance (32 vs 27.7 rows/SM) disappears.
// Per-task math identical to R7/R9 (warp-per-4-rows, f32x2, butterfly reduce,
// warp-autonomous early exit on max|v-u| < TOL).
// ---------------------------------------------------------------------------
#define DR_TOL 1e-3f

__global__ __launch_bounds__(256)
void iter_kernel(const float* __restrict__ bmat,
                 const float* __restrict__ A,
                 const int*   __restrict__ n_iter_ptr,
                 float* __restrict__ out)
{
    extern __shared__ float smem[];
    float* As = smem;          // 32*256
    float* Qs = smem + 8192;   // 32*256
    const int t = threadIdx.x;
    for (int i = t; i < 8192; i += 256) {
        As[i] = A[i];
        Qs[i] = g_Q[i];
    }
    __syncthreads();

    const int lane = t & 31;
    const float4* As4 = (const float4*)As;
    const float4* Qs4 = (const float4*)Qs;
    const int niter = *n_iter_ptr;
    const unsigned FULL = 0xffffffffu;

    while (true) {
        // ---- grab next 4-row task ----
        int task;
        if (lane == 0) task = atomicAdd(&g_ctr, 1);
        task = __shfl_sync(FULL, task, 0);
        if (task >= NTASKS) break;
        const int rowbase = task * 4;

        // ---- load z ----
        float2 z[4][4];
#pragma unroll
        for (int r = 0; r < 4; r++) {
            const float4* y = (const float4*)(g_Y + (size_t)(rowbase + r) * DIMV);
            float4 lo = y[2 * lane];
            float4 hi = y[2 * lane + 1];
            z[r][0] = make_float2(lo.x, lo.y); z[r][1] = make_float2(lo.z, lo.w);
            z[r][2] = make_float2(hi.x, hi.y); z[r][3] = make_float2(hi.z, hi.w);
        }

        // ---- nc = -(b_row @ Q) ----
        float2 nc[4][4];
#pragma unroll
        for (int r = 0; r < 4; r++)
#pragma unroll
            for (int k = 0; k < 4; k++) nc[r][k] = make_float2(0.f, 0.f);
        for (int m = 0; m < MM; m++) {
            float4 qlo = Qs4[m * 64 + 2 * lane];
            float4 qhi = Qs4[m * 64 + 2 * lane + 1];
            float2 q0 = make_float2(qlo.x, qlo.y), q1 = make_float2(qlo.z, qlo.w);
            float2 q2 = make_float2(qhi.x, qhi.y), q3 = make_float2(qhi.z, qhi.w);
#pragma unroll
            for (int r = 0; r < 4; r++) {
                float bv = -bmat[(size_t)(rowbase + r) * MM + m];
                float2 b2 = make_float2(bv, bv);
                nc[r][0] = f2fma(b2, q0, nc[r][0]);
                nc[r][1] = f2fma(b2, q1, nc[r][1]);
                nc[r][2] = f2fma(b2, q2, nc[r][2]);
                nc[r][3] = f2fma(b2, q3, nc[r][3]);
            }
        }

        float2 u[4][4];

        for (int it = 0; ; ++it) {
            // ---- compute u = p_aff(z) ----
            {
                float p0[32], p1[32], p2[32], p3[32];
#pragma unroll
                for (int m = 0; m < 32; m++) {
                    float4 alo = As4[m * 64 + 2 * lane];
                    float4 ahi = As4[m * 64 + 2 * lane + 1];
                    float2 a0 = make_float2(alo.x, alo.y), a1 = make_float2(alo.z, alo.w);
                    float2 a2 = make_float2(ahi.x, ahi.y), a3 = make_float2(ahi.z, ahi.w);
                    float2 pp;
                    pp = f2mul(z[0][0], a0); pp = f2fma(z[0][1], a1, pp);
                    pp = f2fma(z[0][2], a2, pp); pp = f2fma(z[0][3], a3, pp);
                    p0[m] = pp.x + pp.y;
                    pp = f2mul(z[1][0], a0); pp = f2fma(z[1][1], a1, pp);
                    pp = f2fma(z[1][2], a2, pp); pp = f2fma(z[1][3], a3, pp);
                    p1[m] = pp.x + pp.y;
                    pp = f2mul(z[2][0], a0); pp = f2fma(z[2][1], a1, pp);
                    pp = f2fma(z[2][2], a2, pp); pp = f2fma(z[2][3], a3, pp);
                    p2[m] = pp.x + pp.y;
                    pp = f2mul(z[3][0], a0); pp = f2fma(z[3][1], a1, pp);
                    pp = f2fma(z[3][2], a2, pp); pp = f2fma(z[3][3], a3, pp);
                    p3[m] = pp.x + pp.y;
                }
#pragma unroll
                for (int s = 16; s >= 1; s >>= 1) {
#pragma unroll
                    for (int i = 0; i < s; i++) {
                        float aa, bb, send, recv;
                        aa = p0[i]; bb = p0[i + s];
                        send = (lane & s) ? aa : bb; recv = __shfl_xor_sync(FULL, send, s);
                        p0[i] = ((lane & s) ? bb : aa) + recv;
                        aa = p1[i]; bb = p1[i + s];
                        send = (lane & s) ? aa : bb; recv = __shfl_xor_sync(FULL, send, s);
                        p1[i] = ((lane & s) ? bb : aa) + recv;
                        aa = p2[i]; bb = p2[i + s];
                        send = (lane & s) ? aa : bb; recv = __shfl_xor_sync(FULL, send, s);
                        p2[i] = ((lane & s) ? bb : aa) + recv;
                        aa = p3[i]; bb = p3[i + s];
                        send = (lane & s) ? aa : bb; recv = __shfl_xor_sync(FULL, send, s);
                        p3[i] = ((lane & s) ? bb : aa) + recv;
                    }
                }
                const float r0 = p0[0], r1 = p1[0], r2 = p2[0], r3 = p3[0];

                float2 acc[4][4];
#pragma unroll
                for (int r = 0; r < 4; r++)
#pragma unroll
                    for (int k = 0; k < 4; k++) acc[r][k] = nc[r][k];
#pragma unroll
                for (int m = 0; m < 32; m++) {
                    float rm0 = __shfl_sync(FULL, r0, m);
                    float rm1 = __shfl_sync(FULL, r1, m);
                    float rm2 = __shfl_sync(FULL, r2, m);
                    float rm3 = __shfl_sync(FULL, r3, m);
                    float4 qlo = Qs4[m * 64 + 2 * lane];
                    float4 qhi = Qs4[m * 64 + 2 * lane + 1];
                    float2 q0 = make_float2(qlo.x, qlo.y), q1 = make_float2(qlo.z, qlo.w);
                    float2 q2 = make_float2(qhi.x, qhi.y), q3 = make_float2(qhi.z, qhi.w);
                    float2 v;
                    v = make_float2(rm0, rm0);
                    acc[0][0] = f2fma(v, q0, acc[0][0]); acc[0][1] = f2fma(v, q1, acc[0][1]);
                    acc[0][2] = f2fma(v, q2, acc[0][2]); acc[0][3] = f2fma(v, q3, acc[0][3]);
                    v = make_float2(rm1, rm1);
                    acc[1][0] = f2fma(v, q0, acc[1][0]); acc[1][1] = f2fma(v, q1, acc[1][1]);
                    acc[1][2] = f2fma(v, q2, acc[1][2]); acc[1][3] = f2fma(v, q3, acc[1][3]);
                    v = make_float2(rm2, rm2);
                    acc[2][0] = f2fma(v, q0, acc[2][0]); acc[2][1] = f2fma(v, q1, acc[2][1]);
                    acc[2][2] = f2fma(v, q2, acc[2][2]); acc[2][3] = f2fma(v, q3, acc[2][3]);
                    v = make_float2(rm3, rm3);
                    acc[3][0] = f2fma(v, q0, acc[3][0]); acc[3][1] = f2fma(v, q1, acc[3][1]);
                    acc[3][2] = f2fma(v, q2, acc[3][2]); acc[3][3] = f2fma(v, q3, acc[3][3]);
                }
                const float2 NEG1 = make_float2(-1.f, -1.f);
#pragma unroll
                for (int r = 0; r < 4; r++)
#pragma unroll
                    for (int k = 0; k < 4; k++)
                        u[r][k] = f2fma(acc[r][k], NEG1, z[r][k]);
            }

            if (it >= niter) break;

            // ---- z update + residual tracking ----
            float dmax = 0.f;
#pragma unroll
            for (int r = 0; r < 4; r++) {
#pragma unroll
                for (int k = 0; k < 4; k++) {
                    float vx = fminf(fmaxf(2.f * u[r][k].x - z[r][k].x, 0.f), 1.f);
                    float vy = fminf(fmaxf(2.f * u[r][k].y - z[r][k].y, 0.f), 1.f);
                    float dx = vx - u[r][k].x;
                    float dy = vy - u[r][k].y;
                    z[r][k].x = fmaf(1.7f, dx, z[r][k].x);
                    z[r][k].y = fmaf(1.7f, dy, z[r][k].y);
                    dmax = fmaxf(dmax, fabsf(dx));
                    dmax = fmaxf(dmax, fabsf(dy));
                }
            }
            if (__all_sync(FULL, dmax < DR_TOL)) it = niter - 1;
        }

        // ---- store out = p_aff(z_final) = u ----
#pragma unroll
        for (int r = 0; r < 4; r++) {
            float4* o = (float4*)(out + (size_t)(rowbase + r) * DIMV);
            float4 lo, hi;
            lo.x = u[r][0].x; lo.y = u[r][0].y; lo.z = u[r][1].x; lo.w = u[r][1].y;
            hi.x = u[r][2].x; hi.y = u[r][2].y; hi.z = u[r][3].x; hi.w = u[r][3].y;
            o[2 * lane]     = lo;
            o[2 * lane + 1] = hi;
        }
    }
}

// ---------------------------------------------------------------------------
// Launch
// ---------------------------------------------------------------------------
extern "C" void kernel_launch(void* const* d_in, const int* in_sizes, int n_in,
                              void* d_out, int out_size)
{
    const float* x   = (const float*)d_in[0];
    const float* b   = (const float*)d_in[1];
    const float* W1  = (const float*)d_in[2];
    const float* b1  = (const float*)d_in[3];
    const float* W2  = (const float*)d_in[4];
    const float* b2  = (const float*)d_in[5];
    const float* W3  = (const float*)d_in[6];
    const float* b3  = (const float*)d_in[7];
    const float* A   = (const float*)d_in[8];
    const int* n_it  = (const int*)d_in[10];
    float* out = (float*)d_out;

    setup_kernel<<<1, 1024>>>(A);

    float* h1; cudaGetSymbolAddress((void**)&h1, g_H1);
    float* h2; cudaGetSymbolAddress((void**)&h2, g_H2);
    float* y;  cudaGetSymbolAddress((void**)&y,  g_Y);

    gemm_bias_kernel<true ><<<dim3((HID  + 63) / 64, BB / 32), 256>>>(x,  W1, b1, h1, HID,  D_IN);
    gemm_bias_kernel<true ><<<dim3((HID  + 63) / 64, BB / 32), 256>>>(h1, W2, b2, h2, HID,  HID);
    gemm_bias_kernel<false><<<dim3((DIMV + 63) / 64, BB / 32), 256>>>(h2, W3, b3, y,  DIMV, HID);

    // Persistent, work-queue balanced: 148 CTAs x 256 thr, 64KB smem each.
    cudaFuncSetAttribute(iter_kernel, cudaFuncAttributeMaxDynamicSharedMemorySize, 65536);
    iter_kernel<<<148, 256, 65536>>>(b, A, n_it, out);
}

// round 11
// speedup vs baseline: 1.4863x; 1.0371x over previous
#include <cuda_runtime.h>
#include <cstdint>
#include <cstring>

// Problem constants
#define BB     4096
#define D_IN   128
#define HID    200
#define DIMV   256
#define MM     32
#define NTASKS (BB / 2)   // 2 rows per task -> 2048 tasks > 1184 warps

// Scratch (device globals — no allocation allowed)
__device__ float g_H1[BB * HID];
__device__ float g_H2[BB * HID];
__device__ float g_Y [BB * DIMV];
__device__ float g_Q [MM * DIMV];
__device__ int   g_ctr;            // work-queue counter (reset by setup_kernel)

// ---------------------------------------------------------------------------
// Packed f32x2 helpers
// ---------------------------------------------------------------------------
static __device__ __forceinline__ float2 f2fma(float2 a, float2 b, float2 c) {
    unsigned long long ua, ub, uc, ud;
    memcpy(&ua, &a, 8); memcpy(&ub, &b, 8); memcpy(&uc, &c, 8);
    asm("fma.rn.f32x2 %0, %1, %2, %3;" : "=l"(ud) : "l"(ua), "l"(ub), "l"(uc));
    float2 r; memcpy(&r, &ud, 8); return r;
}
static __device__ __forceinline__ float2 f2mul(float2 a, float2 b) {
    unsigned long long ua, ub, ud;
    memcpy(&ua, &a, 8); memcpy(&ub, &b, 8);
    asm("mul.rn.f32x2 %0, %1, %2;" : "=l"(ud) : "l"(ua), "l"(ub));
    float2 r; memcpy(&r, &ud, 8); return r;
}

// ---------------------------------------------------------------------------
// Setup: G = A A^T + 1e-6 I (32x32), Gauss-Jordan inverse, Q = G^{-1} A.
// Also resets the work-queue counter (runs before iter_kernel every launch).
// ---------------------------------------------------------------------------
__global__ void setup_kernel(const float* __restrict__ A)
{
    __shared__ float G[32][65];
    __shared__ float fcol[32];
    const int t = threadIdx.x;
    const int i = t >> 5;
    const int j = t & 31;

    if (t == 0) g_ctr = 0;

    float s = 0.f;
    for (int k = 0; k < DIMV; k++)
        s += A[i * DIMV + k] * A[j * DIMV + k];
    G[i][j]      = s + (i == j ? 1e-6f : 0.f);
    G[i][j + 32] = (i == j) ? 1.f : 0.f;
    __syncthreads();

    for (int k = 0; k < 32; k++) {
        if (j == 0) fcol[i] = G[i][k];
        __syncthreads();
        if (i == k) {
            float inv = 1.f / fcol[k];
            G[k][j]      *= inv;
            G[k][j + 32] *= inv;
        }
        __syncthreads();
        if (i != k) {
            float f = fcol[i];
            G[i][j]      -= f * G[k][j];
            G[i][j + 32] -= f * G[k][j + 32];
        }
        __syncthreads();
    }

    for (int r = 0; r < 8; r++) {
        int idx = t + r * 1024;
        int m = idx >> 8;
        int d = idx & 255;
        float acc = 0.f;
        for (int k = 0; k < 32; k++)
            acc += G[m][32 + k] * A[k * DIMV + d];
        g_Q[m * DIMV + d] = acc;
    }
}

// ---------------------------------------------------------------------------
// Tiled GEMM: Y[M,N] = act(X[M,K] @ W[K,N] + bias)
// R2-proven 64x64x16, 256 threads, 4x4 micro-tile (27.1 us/layer, measured
// twice). Grid = (ceil(N/64), M/64).
// ---------------------------------------------------------------------------
template<bool RELU>
__global__ __launch_bounds__(256)
void gemm_bias_kernel(const float* __restrict__ X, const float* __restrict__ W,
                      const float* __restrict__ bias, float* __restrict__ Y,
                      int Mrows, int N, int K)
{
    __shared__ float Xs[16][68];
    __shared__ float Ws[16][68];
    const int t  = threadIdx.x;
    const int tx = t & 15, ty = t >> 4;
    const int row0 = blockIdx.y * 64;
    const int col0 = blockIdx.x * 64;

    float acc[4][4];
#pragma unroll
    for (int i = 0; i < 4; i++)
#pragma unroll
        for (int j = 0; j < 4; j++) acc[i][j] = 0.f;

    for (int k0 = 0; k0 < K; k0 += 16) {
        {
            int r = t >> 2, q = (t & 3) * 4;
#pragma unroll
            for (int i = 0; i < 4; i++) {
                int kk = q + i;
                float v = 0.f;
                if (k0 + kk < K) v = X[(size_t)(row0 + r) * K + k0 + kk];
                Xs[kk][r] = v;
            }
        }
        {
            int kk = t >> 4, c = (t & 15) * 4;
#pragma unroll
            for (int j = 0; j < 4; j++) {
                float v = 0.f;
                if (k0 + kk < K && col0 + c + j < N)
                    v = W[(size_t)(k0 + kk) * N + col0 + c + j];
                Ws[kk][c + j] = v;
            }
        }
        __syncthreads();
#pragma unroll
        for (int kk = 0; kk < 16; kk++) {
            float a[4], bv[4];
#pragma unroll
            for (int i = 0; i < 4; i++) a[i]  = Xs[kk][ty * 4 + i];
#pragma unroll
            for (int j = 0; j < 4; j++) bv[j] = Ws[kk][tx * 4 + j];
#pragma unroll
            for (int i = 0; i < 4; i++)
#pragma unroll
                for (int j = 0; j < 4; j++)
                    acc[i][j] += a[i] * bv[j];
        }
        __syncthreads();
    }

#pragma unroll
    for (int i = 0; i < 4; i++) {
        int rr = row0 + ty * 4 + i;
        if (rr < Mrows) {
#pragma unroll
            for (int j = 0; j < 4; j++) {
                int cc = col0 + tx * 4 + j;
                if (cc < N) {
                    float v = acc[i][j] + bias[cc];
                    if (RELU) v = fmaxf(v, 0.f);
                    Y[(size_t)rr * N + cc] = v;
                }
            }
        }
    }
}

// ---------------------------------------------------------------------------
// Persistent iteration kernel: grid = 148 CTAs x 256 thr (8 warps/SM).
// 2-ROW tasks: 2048 tasks over 1184 warps -> queue actually loops (~1.73
// tasks/warp) and balances per-SM load to ~13.8 +/- 1 tasks (imbalance 1.05
// vs 1.16 for R10's one-task-per-warp degenerate case).
// Crossbar co-saturation: 128 LDS.128/pass (4096 cyc/SM) == FMA 512 FFMA2 x
// rt4 x 2 warps (4096 cyc/SMSP) -> per-row throughput preserved.
// TOL = 5e-3: rel_err measured 1.03e-6 at this TOL in R8 (error floor).
// ---------------------------------------------------------------------------
#define DR_TOL 5e-3f

__global__ __launch_bounds__(256)
void iter_kernel(const float* __restrict__ bmat,
                 const float* __restrict__ A,
                 const int*   __restrict__ n_iter_ptr,
                 float* __restrict__ out)
{
    extern __shared__ float smem[];
    float* As = smem;          // 32*256
    float* Qs = smem + 8192;   // 32*256
    const int t = threadIdx.x;
    for (int i = t; i < 8192; i += 256) {
        As[i] = A[i];
        Qs[i] = g_Q[i];
    }
    __syncthreads();

    const int lane = t & 31;
    const float4* As4 = (const float4*)As;
    const float4* Qs4 = (const float4*)Qs;
    const int niter = *n_iter_ptr;
    const unsigned FULL = 0xffffffffu;

    while (true) {
        // ---- grab next 2-row task ----
        int task;
        if (lane == 0) task = atomicAdd(&g_ctr, 1);
        task = __shfl_sync(FULL, task, 0);
        if (task >= NTASKS) break;
        const int rowbase = task * 2;

        // ---- load z ----
        float2 z[2][4];
#pragma unroll
        for (int r = 0; r < 2; r++) {
            const float4* y = (const float4*)(g_Y + (size_t)(rowbase + r) * DIMV);
            float4 lo = y[2 * lane];
            float4 hi = y[2 * lane + 1];
            z[r][0] = make_float2(lo.x, lo.y); z[r][1] = make_float2(lo.z, lo.w);
            z[r][2] = make_float2(hi.x, hi.y); z[r][3] = make_float2(hi.z, hi.w);
        }

        // ---- nc = -(b_row @ Q) ----
        float2 nc[2][4];
#pragma unroll
        for (int r = 0; r < 2; r++)
#pragma unroll
            for (int k = 0; k < 4; k++) nc[r][k] = make_float2(0.f, 0.f);
        for (int m = 0; m < MM; m++) {
            float4 qlo = Qs4[m * 64 + 2 * lane];
            float4 qhi = Qs4[m * 64 + 2 * lane + 1];
            float2 q0 = make_float2(qlo.x, qlo.y), q1 = make_float2(qlo.z, qlo.w);
            float2 q2 = make_float2(qhi.x, qhi.y), q3 = make_float2(qhi.z, qhi.w);
#pragma unroll
            for (int r = 0; r < 2; r++) {
                float bv = -bmat[(size_t)(rowbase + r) * MM + m];
                float2 b2 = make_float2(bv, bv);
                nc[r][0] = f2fma(b2, q0, nc[r][0]);
                nc[r][1] = f2fma(b2, q1, nc[r][1]);
                nc[r][2] = f2fma(b2, q2, nc[r][2]);
                nc[r][3] = f2fma(b2, q3, nc[r][3]);
            }
        }

        float2 u[2][4];

        for (int it = 0; ; ++it) {
            // ---- compute u = p_aff(z) ----
            {
                float p0[32], p1[32];
#pragma unroll
                for (int m = 0; m < 32; m++) {
                    float4 alo = As4[m * 64 + 2 * lane];
                    float4 ahi = As4[m * 64 + 2 * lane + 1];
                    float2 a0 = make_float2(alo.x, alo.y), a1 = make_float2(alo.z, alo.w);
                    float2 a2 = make_float2(ahi.x, ahi.y), a3 = make_float2(ahi.z, ahi.w);
                    float2 pp;
                    pp = f2mul(z[0][0], a0); pp = f2fma(z[0][1], a1, pp);
                    pp = f2fma(z[0][2], a2, pp); pp = f2fma(z[0][3], a3, pp);
                    p0[m] = pp.x + pp.y;
                    pp = f2mul(z[1][0], a0); pp = f2fma(z[1][1], a1, pp);
                    pp = f2fma(z[1][2], a2, pp); pp = f2fma(z[1][3], a3, pp);
                    p1[m] = pp.x + pp.y;
                }
#pragma unroll
                for (int s = 16; s >= 1; s >>= 1) {
#pragma unroll
                    for (int i = 0; i < s; i++) {
                        float aa, bb, send, recv;
                        aa = p0[i]; bb = p0[i + s];
                        send = (lane & s) ? aa : bb; recv = __shfl_xor_sync(FULL, send, s);
                        p0[i] = ((lane & s) ? bb : aa) + recv;
                        aa = p1[i]; bb = p1[i + s];
                        send = (lane & s) ? aa : bb; recv = __shfl_xor_sync(FULL, send, s);
                        p1[i] = ((lane & s) ? bb : aa) + recv;
                    }
                }
                const float r0 = p0[0], r1 = p1[0];

                float2 acc[2][4];
#pragma unroll
                for (int r = 0; r < 2; r++)
#pragma unroll
                    for (int k = 0; k < 4; k++) acc[r][k] = nc[r][k];
#pragma unroll
                for (int m = 0; m < 32; m++) {
                    float rm0 = __shfl_sync(FULL, r0, m);
                    float rm1 = __shfl_sync(FULL, r1, m);
                    float4 qlo = Qs4[m * 64 + 2 * lane];
                    float4 qhi = Qs4[m * 64 + 2 * lane + 1];
                    float2 q0 = make_float2(qlo.x, qlo.y), q1 = make_float2(qlo.z, qlo.w);
                    float2 q2 = make_float2(qhi.x, qhi.y), q3 = make_float2(qhi.z, qhi.w);
                    float2 v;
                    v = make_float2(rm0, rm0);
                    acc[0][0] = f2fma(v, q0, acc[0][0]); acc[0][1] = f2fma(v, q1, acc[0][1]);
                    acc[0][2] = f2fma(v, q2, acc[0][2]); acc[0][3] = f2fma(v, q3, acc[0][3]);
                    v = make_float2(rm1, rm1);
                    acc[1][0] = f2fma(v, q0, acc[1][0]); acc[1][1] = f2fma(v, q1, acc[1][1]);
                    acc[1][2] = f2fma(v, q2, acc[1][2]); acc[1][3] = f2fma(v, q3, acc[1][3]);
                }
                const float2 NEG1 = make_float2(-1.f, -1.f);
#pragma unroll
                for (int r = 0; r < 2; r++)
#pragma unroll
                    for (int k = 0; k < 4; k++)
                        u[r][k] = f2fma(acc[r][k], NEG1, z[r][k]);
            }

            if (it >= niter) break;

            // ---- z update + residual tracking ----
            float dmax = 0.f;
#pragma unroll
            for (int r = 0; r < 2; r++) {
#pragma unroll
                for (int k = 0; k < 4; k++) {
                    float vx = fminf(fmaxf(2.f * u[r][k].x - z[r][k].x, 0.f), 1.f);
                    float vy = fminf(fmaxf(2.f * u[r][k].y - z[r][k].y, 0.f), 1.f);
                    float dx = vx - u[r][k].x;
                    float dy = vy - u[r][k].y;
                    z[r][k].x = fmaf(1.7f, dx, z[r][k].x);
                    z[r][k].y = fmaf(1.7f, dy, z[r][k].y);
                    dmax = fmaxf(dmax, fabsf(dx));
                    dmax = fmaxf(dmax, fabsf(dy));
                }
            }
            if (__all_sync(FULL, dmax < DR_TOL)) it = niter - 1;
        }

        // ---- store out = p_aff(z_final) = u ----
#pragma unroll
        for (int r = 0; r < 2; r++) {
            float4* o = (float4*)(out + (size_t)(rowbase + r) * DIMV);
            float4 lo, hi;
            lo.x = u[r][0].x; lo.y = u[r][0].y; lo.z = u[r][1].x; lo.w = u[r][1].y;
            hi.x = u[r][2].x; hi.y = u[r][2].y; hi.z = u[r][3].x; hi.w = u[r][3].y;
            o[2 * lane]     = lo;
            o[2 * lane + 1] = hi;
        }
    }
}

// ---------------------------------------------------------------------------
// Launch
// ---------------------------------------------------------------------------
extern "C" void kernel_launch(void* const* d_in, const int* in_sizes, int n_in,
                              void* d_out, int out_size)
{
    const float* x   = (const float*)d_in[0];
    const float* b   = (const float*)d_in[1];
    const float* W1  = (const float*)d_in[2];
    const float* b1  = (const float*)d_in[3];
    const float* W2  = (const float*)d_in[4];
    const float* b2  = (const float*)d_in[5];
    const float* W3  = (const float*)d_in[6];
    const float* b3  = (const float*)d_in[7];
    const float* A   = (const float*)d_in[8];
    const int* n_it  = (const int*)d_in[10];
    float* out = (float*)d_out;

    setup_kernel<<<1, 1024>>>(A);

    float* h1; cudaGetSymbolAddress((void**)&h1, g_H1);
    float* h2; cudaGetSymbolAddress((void**)&h2, g_H2);
    float* y;  cudaGetSymbolAddress((void**)&y,  g_Y);

    gemm_bias_kernel<true ><<<dim3((HID  + 63) / 64, BB / 64), 256>>>(x,  W1, b1, h1, BB, HID,  D_IN);
    gemm_bias_kernel<true ><<<dim3((HID  + 63) / 64, BB / 64), 256>>>(h1, W2, b2, h2, BB, HID,  HID);
    gemm_bias_kernel<false><<<dim3((DIMV + 63) / 64, BB / 64), 256>>>(h2, W3, b3, y,  BB, DIMV, HID);

    // Persistent, work-queue balanced: 148 CTAs x 256 thr, 64KB smem each.
    cudaFuncSetAttribute(iter_kernel, cudaFuncAttributeMaxDynamicSharedMemorySize, 65536);
    iter_kernel<<<148, 256, 65536>>>(b, A, n_it, out);
}

// round 12
// speedup vs baseline: 1.5778x; 1.0616x over previous
#include <cuda_runtime.h>
#include <cstdint>
#include <cstring>

// Problem constants
#define BB     4096
#define D_IN   128
#define HID    200
#define DIMV   256
#define MM     32
#define NTASKS (BB / 2)   // 2 rows per task

// Scratch (device globals — no allocation allowed)
__device__ float g_H1[BB * HID];
__device__ float g_H2[BB * HID];
__device__ float g_Y [BB * DIMV];
__device__ float g_Q [MM * DIMV];
__device__ int   g_ctr;            // work-queue counter (reset by setup_kernel)

// ---------------------------------------------------------------------------
// Packed f32x2 helpers
// ---------------------------------------------------------------------------
static __device__ __forceinline__ float2 f2fma(float2 a, float2 b, float2 c) {
    unsigned long long ua, ub, uc, ud;
    memcpy(&ua, &a, 8); memcpy(&ub, &b, 8); memcpy(&uc, &c, 8);
    asm("fma.rn.f32x2 %0, %1, %2, %3;" : "=l"(ud) : "l"(ua), "l"(ub), "l"(uc));
    float2 r; memcpy(&r, &ud, 8); return r;
}
static __device__ __forceinline__ float2 f2mul(float2 a, float2 b) {
    unsigned long long ua, ub, ud;
    memcpy(&ua, &a, 8); memcpy(&ub, &b, 8);
    asm("mul.rn.f32x2 %0, %1, %2;" : "=l"(ud) : "l"(ua), "l"(ub));
    float2 r; memcpy(&r, &ud, 8); return r;
}

// ---------------------------------------------------------------------------
// tf32 helpers: split x = hi + lo (each tf32), 3xTF32 gives ~fp32 accuracy.
// ---------------------------------------------------------------------------
static __device__ __forceinline__ void tf32_split(float x, uint32_t& hi, uint32_t& lo) {
    uint32_t h;
    asm("cvt.rna.tf32.f32 %0, %1;" : "=r"(h) : "f"(x));
    float l = x - __uint_as_float(h);
    uint32_t lw;
    asm("cvt.rna.tf32.f32 %0, %1;" : "=r"(lw) : "f"(l));
    hi = h; lo = lw;
}
static __device__ __forceinline__ void mma_tf32(float c[4], const uint32_t a[4], const uint32_t b[2]) {
    asm("mma.sync.aligned.m16n8k8.row.col.f32.tf32.tf32.f32 "
        "{%0,%1,%2,%3}, {%4,%5,%6,%7}, {%8,%9}, {%0,%1,%2,%3};"
        : "+f"(c[0]), "+f"(c[1]), "+f"(c[2]), "+f"(c[3])
        : "r"(a[0]), "r"(a[1]), "r"(a[2]), "r"(a[3]), "r"(b[0]), "r"(b[1]));
}

// ---------------------------------------------------------------------------
// Setup: G = A A^T + 1e-6 I (32x32), Gauss-Jordan inverse, Q = G^{-1} A.
// Also resets the work-queue counter.
// ---------------------------------------------------------------------------
__global__ void setup_kernel(const float* __restrict__ A)
{
    __shared__ float G[32][65];
    __shared__ float fcol[32];
    const int t = threadIdx.x;
    const int i = t >> 5;
    const int j = t & 31;

    if (t == 0) g_ctr = 0;

    float s = 0.f;
    for (int k = 0; k < DIMV; k++)
        s += A[i * DIMV + k] * A[j * DIMV + k];
    G[i][j]      = s + (i == j ? 1e-6f : 0.f);
    G[i][j + 32] = (i == j) ? 1.f : 0.f;
    __syncthreads();

    for (int k = 0; k < 32; k++) {
        if (j == 0) fcol[i] = G[i][k];
        __syncthreads();
        if (i == k) {
            float inv = 1.f / fcol[k];
            G[k][j]      *= inv;
            G[k][j + 32] *= inv;
        }
        __syncthreads();
        if (i != k) {
            float f = fcol[i];
            G[i][j]      -= f * G[k][j];
            G[i][j + 32] -= f * G[k][j + 32];
        }
        __syncthreads();
    }

    for (int r = 0; r < 8; r++) {
        int idx = t + r * 1024;
        int m = idx >> 8;
        int d = idx & 255;
        float acc = 0.f;
        for (int k = 0; k < 32; k++)
            acc += G[m][32 + k] * A[k * DIMV + d];
        g_Q[m * DIMV + d] = acc;
    }
}

// ---------------------------------------------------------------------------
// 3xTF32 tensor-core GEMM: Y[M,N] = act(X[M,K] @ W[K,N] + bias)
// BM=64, BN=64, BK=32, 256 thr = 8 warps, warp tile 32x16 (2x2 m16n8k8).
// Smem pads: Xs stride 36 (A-frag reads bank-bijective), Ws stride 72
// ((8k+n) mod 32 bijective for B-frag reads). K,N multiples of 4 (128/200/256).
// ---------------------------------------------------------------------------
template<bool RELU>
__global__ __launch_bounds__(256)
void gemm_tf32_kernel(const float* __restrict__ X, const float* __restrict__ W,
                      const float* __restrict__ bias, float* __restrict__ Y,
                      int N, int K)
{
    __shared__ float Xs[64][36];
    __shared__ float Ws[32][72];
    const int t    = threadIdx.x;
    const int lane = t & 31;
    const int wid  = t >> 5;
    const int row0 = blockIdx.y * 64;
    const int col0 = blockIdx.x * 64;
    const int wm = (wid & 1) * 32;   // warp row base within CTA tile
    const int wn = (wid >> 1) * 16;  // warp col base within CTA tile
    const int lr = lane >> 2;        // 0..7
    const int lc = lane & 3;         // 0..3

    float c[2][2][4];
#pragma unroll
    for (int mt = 0; mt < 2; mt++)
#pragma unroll
        for (int nt = 0; nt < 2; nt++)
#pragma unroll
            for (int q = 0; q < 4; q++) c[mt][nt][q] = 0.f;

    const int nkt = (K + 31) / 32;
    for (int kt = 0; kt < nkt; kt++) {
        const int kbase = kt * 32;
        // X tile: 64 rows x 32 k (512 float4, 2 per thread)
#pragma unroll
        for (int l = 0; l < 2; l++) {
            int idx = t + l * 256;
            int r = idx >> 3;
            int q = idx & 7;
            int kk = kbase + q * 4;
            float4 v = make_float4(0.f, 0.f, 0.f, 0.f);
            if (kk + 4 <= K) v = *(const float4*)&X[(size_t)(row0 + r) * K + kk];
            *(float4*)&Xs[r][q * 4] = v;
        }
        // W tile: 32 k x 64 n (512 float4, 2 per thread)
#pragma unroll
        for (int l = 0; l < 2; l++) {
            int idx = t + l * 256;
            int k = idx >> 4;
            int cq = idx & 15;
            int gk = kbase + k;
            int gc = col0 + cq * 4;
            float4 v = make_float4(0.f, 0.f, 0.f, 0.f);
            if (gk < K && gc + 4 <= N) v = *(const float4*)&W[(size_t)gk * N + gc];
            *(float4*)&Ws[k][cq * 4] = v;
        }
        __syncthreads();

#pragma unroll
        for (int ks = 0; ks < 4; ks++) {
            const int k0 = ks * 8;
            // A fragments (2 m-tiles), split hi/lo
            uint32_t ahi[2][4], alo[2][4];
#pragma unroll
            for (int mt = 0; mt < 2; mt++) {
                int rb = wm + mt * 16;
                float a0 = Xs[rb + lr    ][k0 + lc    ];
                float a1 = Xs[rb + lr + 8][k0 + lc    ];
                float a2 = Xs[rb + lr    ][k0 + lc + 4];
                float a3 = Xs[rb + lr + 8][k0 + lc + 4];
                tf32_split(a0, ahi[mt][0], alo[mt][0]);
                tf32_split(a1, ahi[mt][1], alo[mt][1]);
                tf32_split(a2, ahi[mt][2], alo[mt][2]);
                tf32_split(a3, ahi[mt][3], alo[mt][3]);
            }
            // B fragments (2 n-tiles), split hi/lo
            uint32_t bhi[2][2], blo[2][2];
#pragma unroll
            for (int nt = 0; nt < 2; nt++) {
                int cb = wn + nt * 8;
                float b0 = Ws[k0 + lc    ][cb + lr];
                float b1 = Ws[k0 + lc + 4][cb + lr];
                tf32_split(b0, bhi[nt][0], blo[nt][0]);
                tf32_split(b1, bhi[nt][1], blo[nt][1]);
            }
            // 3xTF32: hi*hi + hi*lo + lo*hi
#pragma unroll
            for (int mt = 0; mt < 2; mt++)
#pragma unroll
                for (int nt = 0; nt < 2; nt++) {
                    mma_tf32(c[mt][nt], ahi[mt], bhi[nt]);
                    mma_tf32(c[mt][nt], ahi[mt], blo[nt]);
                    mma_tf32(c[mt][nt], alo[mt], bhi[nt]);
                }
        }
        __syncthreads();
    }

    // Epilogue: bias + relu, store per C-fragment layout
#pragma unroll
    for (int mt = 0; mt < 2; mt++) {
#pragma unroll
        for (int nt = 0; nt < 2; nt++) {
            int row = row0 + wm + mt * 16 + lr;
            int col = col0 + wn + nt * 8 + 2 * lc;
            if (col < N) {   // N even, col even -> col+1 < N too
                float bv0 = bias[col], bv1 = bias[col + 1];
                float v0 = c[mt][nt][0] + bv0;
                float v1 = c[mt][nt][1] + bv1;
                float v2 = c[mt][nt][2] + bv0;
                float v3 = c[mt][nt][3] + bv1;
                if (RELU) {
                    v0 = fmaxf(v0, 0.f); v1 = fmaxf(v1, 0.f);
                    v2 = fmaxf(v2, 0.f); v3 = fmaxf(v3, 0.f);
                }
                Y[(size_t)row * N + col]           = v0;
                Y[(size_t)row * N + col + 1]       = v1;
                Y[(size_t)(row + 8) * N + col]     = v2;
                Y[(size_t)(row + 8) * N + col + 1] = v3;
            }
        }
    }
}

// ---------------------------------------------------------------------------
// Persistent iteration kernel (byte-identical to R11): 148 CTAs x 256 thr,
// 2-row tasks from a global atomic queue, f32x2 math, butterfly reduce,
// warp-autonomous early exit. TOL=5e-3 (rel_err floor ~1.0e-6, measured 2x).
// ---------------------------------------------------------------------------
#define DR_TOL 5e-3f

__global__ __launch_bounds__(256)
void iter_kernel(const float* __restrict__ bmat,
                 const float* __restrict__ A,
                 const int*   __restrict__ n_iter_ptr,
                 float* __restrict__ out)
{
    extern __shared__ float smem[];
    float* As = smem;          // 32*256
    float* Qs = smem + 8192;   // 32*256
    const int t = threadIdx.x;
    for (int i = t; i < 8192; i += 256) {
        As[i] = A[i];
        Qs[i] = g_Q[i];
    }
    __syncthreads();

    const int lane = t & 31;
    const float4* As4 = (const float4*)As;
    const float4* Qs4 = (const float4*)Qs;
    const int niter = *n_iter_ptr;
    const unsigned FULL = 0xffffffffu;

    while (true) {
        int task;
        if (lane == 0) task = atomicAdd(&g_ctr, 1);
        task = __shfl_sync(FULL, task, 0);
        if (task >= NTASKS) break;
        const int rowbase = task * 2;

        float2 z[2][4];
#pragma unroll
        for (int r = 0; r < 2; r++) {
            const float4* y = (const float4*)(g_Y + (size_t)(rowbase + r) * DIMV);
            float4 lo = y[2 * lane];
            float4 hi = y[2 * lane + 1];
            z[r][0] = make_float2(lo.x, lo.y); z[r][1] = make_float2(lo.z, lo.w);
            z[r][2] = make_float2(hi.x, hi.y); z[r][3] = make_float2(hi.z, hi.w);
        }

        float2 nc[2][4];
#pragma unroll
        for (int r = 0; r < 2; r++)
#pragma unroll
            for (int k = 0; k < 4; k++) nc[r][k] = make_float2(0.f, 0.f);
        for (int m = 0; m < MM; m++) {
            float4 qlo = Qs4[m * 64 + 2 * lane];
            float4 qhi = Qs4[m * 64 + 2 * lane + 1];
            float2 q0 = make_float2(qlo.x, qlo.y), q1 = make_float2(qlo.z, qlo.w);
            float2 q2 = make_float2(qhi.x, qhi.y), q3 = make_float2(qhi.z, qhi.w);
#pragma unroll
            for (int r = 0; r < 2; r++) {
                float bv = -bmat[(size_t)(rowbase + r) * MM + m];
                float2 b2 = make_float2(bv, bv);
                nc[r][0] = f2fma(b2, q0, nc[r][0]);
                nc[r][1] = f2fma(b2, q1, nc[r][1]);
                nc[r][2] = f2fma(b2, q2, nc[r][2]);
                nc[r][3] = f2fma(b2, q3, nc[r][3]);
            }
        }

        float2 u[2][4];

        for (int it = 0; ; ++it) {
            {
                float p0[32], p1[32];
#pragma unroll
                for (int m = 0; m < 32; m++) {
                    float4 alo = As4[m * 64 + 2 * lane];
                    float4 ahi = As4[m * 64 + 2 * lane + 1];
                    float2 a0 = make_float2(alo.x, alo.y), a1 = make_float2(alo.z, alo.w);
                    float2 a2 = make_float2(ahi.x, ahi.y), a3 = make_float2(ahi.z, ahi.w);
                    float2 pp;
                    pp = f2mul(z[0][0], a0); pp = f2fma(z[0][1], a1, pp);
                    pp = f2fma(z[0][2], a2, pp); pp = f2fma(z[0][3], a3, pp);
                    p0[m] = pp.x + pp.y;
                    pp = f2mul(z[1][0], a0); pp = f2fma(z[1][1], a1, pp);
                    pp = f2fma(z[1][2], a2, pp); pp = f2fma(z[1][3], a3, pp);
                    p1[m] = pp.x + pp.y;
                }
#pragma unroll
                for (int s = 16; s >= 1; s >>= 1) {
#pragma unroll
                    for (int i = 0; i < s; i++) {
                        float aa, bb, send, recv;
                        aa = p0[i]; bb = p0[i + s];
                        send = (lane & s) ? aa : bb; recv = __shfl_xor_sync(FULL, send, s);
                        p0[i] = ((lane & s) ? bb : aa) + recv;
                        aa = p1[i]; bb = p1[i + s];
                        send = (lane & s) ? aa : bb; recv = __shfl_xor_sync(FULL, send, s);
                        p1[i] = ((lane & s) ? bb : aa) + recv;
                    }
                }
                const float r0 = p0[0], r1 = p1[0];

                float2 acc[2][4];
#pragma unroll
                for (int r = 0; r < 2; r++)
#pragma unroll
                    for (int k = 0; k < 4; k++) acc[r][k] = nc[r][k];
#pragma unroll
                for (int m = 0; m < 32; m++) {
                    float rm0 = __shfl_sync(FULL, r0, m);
                    float rm1 = __shfl_sync(FULL, r1, m);
                    float4 qlo = Qs4[m * 64 + 2 * lane];
                    float4 qhi = Qs4[m * 64 + 2 * lane + 1];
                    float2 q0 = make_float2(qlo.x, qlo.y), q1 = make_float2(qlo.z, qlo.w);
                    float2 q2 = make_float2(qhi.x, qhi.y), q3 = make_float2(qhi.z, qhi.w);
                    float2 v;
                    v = make_float2(rm0, rm0);
                    acc[0][0] = f2fma(v, q0, acc[0][0]); acc[0][1] = f2fma(v, q1, acc[0][1]);
                    acc[0][2] = f2fma(v, q2, acc[0][2]); acc[0][3] = f2fma(v, q3, acc[0][3]);
                    v = make_float2(rm1, rm1);
                    acc[1][0] = f2fma(v, q0, acc[1][0]); acc[1][1] = f2fma(v, q1, acc[1][1]);
                    acc[1][2] = f2fma(v, q2, acc[1][2]); acc[1][3] = f2fma(v, q3, acc[1][3]);
                }
                const float2 NEG1 = make_float2(-1.f, -1.f);
#pragma unroll
                for (int r = 0; r < 2; r++)
#pragma unroll
                    for (int k = 0; k < 4; k++)
                        u[r][k] = f2fma(acc[r][k], NEG1, z[r][k]);
            }

            if (it >= niter) break;

            float dmax = 0.f;
#pragma unroll
            for (int r = 0; r < 2; r++) {
#pragma unroll
                for (int k = 0; k < 4; k++) {
                    float vx = fminf(fmaxf(2.f * u[r][k].x - z[r][k].x, 0.f), 1.f);
                    float vy = fminf(fmaxf(2.f * u[r][k].y - z[r][k].y, 0.f), 1.f);
                    float dx = vx - u[r][k].x;
                    float dy = vy - u[r][k].y;
                    z[r][k].x = fmaf(1.7f, dx, z[r][k].x);
                    z[r][k].y = fmaf(1.7f, dy, z[r][k].y);
                    dmax = fmaxf(dmax, fabsf(dx));
                    dmax = fmaxf(dmax, fabsf(dy));
                }
            }
            if (__all_sync(FULL, dmax < DR_TOL)) it = niter - 1;
        }

#pragma unroll
        for (int r = 0; r < 2; r++) {
            float4* o = (float4*)(out + (size_t)(rowbase + r) * DIMV);
            float4 lo, hi;
            lo.x = u[r][0].x; lo.y = u[r][0].y; lo.z = u[r][1].x; lo.w = u[r][1].y;
            hi.x = u[r][2].x; hi.y = u[r][2].y; hi.z = u[r][3].x; hi.w = u[r][3].y;
            o[2 * lane]     = lo;
            o[2 * lane + 1] = hi;
        }
    }
}

// ---------------------------------------------------------------------------
// Launch
// ---------------------------------------------------------------------------
extern "C" void kernel_launch(void* const* d_in, const int* in_sizes, int n_in,
                              void* d_out, int out_size)
{
    const float* x   = (const float*)d_in[0];
    const float* b   = (const float*)d_in[1];
    const float* W1  = (const float*)d_in[2];
    const float* b1  = (const float*)d_in[3];
    const float* W2  = (const float*)d_in[4];
    const float* b2  = (const float*)d_in[5];
    const float* W3  = (const float*)d_in[6];
    const float* b3  = (const float*)d_in[7];
    const float* A   = (const float*)d_in[8];
    const int* n_it  = (const int*)d_in[10];
    float* out = (float*)d_out;

    setup_kernel<<<1, 1024>>>(A);

    float* h1; cudaGetSymbolAddress((void**)&h1, g_H1);
    float* h2; cudaGetSymbolAddress((void**)&h2, g_H2);
    float* y;  cudaGetSymbolAddress((void**)&y,  g_Y);

    // 3xTF32 tensor MLP: grid (ceil(N/64), 4096/64)
    gemm_tf32_kernel<true ><<<dim3((HID  + 63) / 64, BB / 64), 256>>>(x,  W1, b1, h1, HID,  D_IN);
    gemm_tf32_kernel<true ><<<dim3((HID  + 63) / 64, BB / 64), 256>>>(h1, W2, b2, h2, HID,  HID);
    gemm_tf32_kernel<false><<<dim3((DIMV + 63) / 64, BB / 64), 256>>>(h2, W3, b3, y,  DIMV, HID);

    // Persistent, work-queue balanced iteration: 148 CTAs x 256 thr.
    cudaFuncSetAttribute(iter_kernel, cudaFuncAttributeMaxDynamicSharedMemorySize, 65536);
    iter_kernel<<<148, 256, 65536>>>(b, A, n_it, out);
}